// round 14
// baseline (speedup 1.0000x reference)
#include <cuda_runtime.h>
#include <cuda_bf16.h>

// Spread accumulator/ticket slots: one 128-byte L2 line each, so no address
// ever sees more than 128 atomic ops (R11: 16K ops on ONE line poisons the
// chip; R12: 16K ops over 128 lines is free). Zero-initialized; the final
// completer resets everything for CUDA-graph replay determinism.
#define NSLOTS 128
__device__ float        g_partial[NSLOTS][32];  // [slot][pad] — use [slot][0]
__device__ unsigned int g_ticket [NSLOTS][32];  // per-slot arrival counters
__device__ unsigned int g_done = 0u;            // slot-completion counter (<=128 ops)

// One CTA per segment, 128 threads — R12's proven ~6.6TB/s streaming body.
// In-kernel finalize via hierarchical spread tickets (no second kernel: a
// dependent launch costs a fixed ~4.5us floor in this harness).
__global__ __launch_bounds__(128, 16) void listnet_fused_kernel(
    const float* __restrict__ mean,
    const float* __restrict__ variance,
    const float* __restrict__ targets,
    const int*   __restrict__ scope,
    float* __restrict__ out,
    int seg_len, int num_seg)
{
    const int seg = blockIdx.x;
    const int tid = threadIdx.x;           // 0..127
    const long long base = (long long)seg * seg_len;

    const float4* __restrict__ m4 = reinterpret_cast<const float4*>(mean + base);
    const float4* __restrict__ v4 = reinterpret_cast<const float4*>(variance + base);
    const float4* __restrict__ t4 = reinterpret_cast<const float4*>(targets + base);

    float s1 = 0.0f;  // sum exp(a),  a = x + 0.5 y
    float s2 = 0.0f;  // sum exp(t)
    float s3 = 0.0f;  // sum exp(t) * b,  b = x - 0.5 y

    const int nvec = seg_len >> 2;         // float4s per segment (128 for 512)
    for (int i = tid; i < nvec; i += 128) {
        float4 m = m4[i];
        float4 v = v4[i];
        float4 t = t4[i];

        { float h = 0.5f * v.x; float a = m.x + h, b = m.x - h;
          float ea = __expf(a), et = __expf(t.x);
          s1 += ea; s2 += et; s3 += et * b; }
        { float h = 0.5f * v.y; float a = m.y + h, b = m.y - h;
          float ea = __expf(a), et = __expf(t.y);
          s1 += ea; s2 += et; s3 += et * b; }
        { float h = 0.5f * v.z; float a = m.z + h, b = m.z - h;
          float ea = __expf(a), et = __expf(t.z);
          s1 += ea; s2 += et; s3 += et * b; }
        { float h = 0.5f * v.w; float a = m.w + h, b = m.w - h;
          float ea = __expf(a), et = __expf(t.w);
          s1 += ea; s2 += et; s3 += et * b; }
    }

    // Warp reduction (3 values)
    #pragma unroll
    for (int off = 16; off > 0; off >>= 1) {
        s1 += __shfl_down_sync(0xFFFFFFFFu, s1, off);
        s2 += __shfl_down_sync(0xFFFFFFFFu, s2, off);
        s3 += __shfl_down_sync(0xFFFFFFFFu, s3, off);
    }

    __shared__ float sh1[4], sh2[4], sh3[4];
    const int warp = tid >> 5;
    const int lane = tid & 31;
    if (lane == 0) { sh1[warp] = s1; sh2[warp] = s2; sh3[warp] = s3; }
    __syncthreads();

    if (tid == 0) {
        float S1 = sh1[0] + sh1[1] + sh1[2] + sh1[3];
        float S2 = sh2[0] + sh2[1] + sh2[2] + sh2[3];
        float S3 = sh3[0] + sh3[1] + sh3[2] + sh3[3];
        // per_seg = (log(S1) - S3/S2) / scope[seg]
        float val = (__logf(S1) - S3 / S2) / (float)scope[seg];

        const int slot = seg & (NSLOTS - 1);
        const unsigned int per_slot = (unsigned int)(num_seg / NSLOTS); // 128

        // L0: fire-and-forget RED.ADD to the spread slot (proven harmless).
        atomicAdd(&g_partial[slot][0], val);

        // L1: spread ticket, acq_rel — same-address RMW chain orders each
        // CTA's partial-RED before the slot-completion observation.
        unsigned int old;
        asm volatile("atom.add.acq_rel.gpu.u32 %0, [%1], 1;"
                     : "=r"(old) : "l"(&g_ticket[slot][0]) : "memory");

        if (old == per_slot - 1u) {
            // L2: slot complete -> bump the (low-traffic) done counter.
            unsigned int old2;
            asm volatile("atom.add.acq_rel.gpu.u32 %0, [%1], 1;"
                         : "=r"(old2) : "l"(&g_done) : "memory");

            if (old2 == (unsigned int)NSLOTS - 1u) {
                // All slots complete and all partials visible (acq_rel chain).
                float s = 0.0f;
                #pragma unroll 16
                for (int k = 0; k < NSLOTS; k++) {
                    float p;
                    asm volatile("ld.acquire.gpu.f32 %0, [%1];"
                                 : "=f"(p) : "l"(&g_partial[k][0]) : "memory");
                    s += p;
                    g_partial[k][0] = 0.0f;   // reset for next replay
                    g_ticket[k][0]  = 0u;
                }
                out[0] = s / (float)num_seg;
                g_done = 0u;
            }
        }
    }
}

extern "C" void kernel_launch(void* const* d_in, const int* in_sizes, int n_in,
                              void* d_out, int out_size)
{
    // metadata order: mean (N), variance (N), scope (NUM_SEG), targets (N)
    const float* mean     = (const float*)d_in[0];
    const float* variance = (const float*)d_in[1];
    const int*   scope    = (const int*)  d_in[2];
    const float* targets  = (const float*)d_in[3];
    float* out = (float*)d_out;

    const int n       = in_sizes[0];
    const int num_seg = in_sizes[2];
    const int seg_len = n / num_seg;   // 512 for this dataset

    listnet_fused_kernel<<<num_seg, 128>>>(mean, variance, targets, scope, out,
                                           seg_len, num_seg);
}

// round 15
// speedup vs baseline: 2.0727x; 2.0727x over previous
#include <cuda_runtime.h>
#include <cuda_bf16.h>

// Spread slots: one 128B L2 line each -> max 128 atomic ops per address.
// Poison table (measured): single-address atomics = L2 serialization poison;
// per-CTA acquire = L1-invalidate poison. This design uses neither.
#define NSLOTS 128
__device__ float        g_partial[NSLOTS][32];  // [slot][pad] — use [slot][0]
__device__ unsigned int g_ticket [NSLOTS][32];  // per-slot arrival counters
__device__ unsigned int g_done = 0u;            // slot completions (<=128 ops)

// One CTA per segment, 128 threads — R12's proven ~6.6TB/s streaming body,
// with an in-kernel finalize built ONLY from proven-benign per-CTA ops:
// relaxed spread RED + release spread ticket. Acquire happens exactly once.
__global__ __launch_bounds__(128, 16) void listnet_fused_kernel(
    const float* __restrict__ mean,
    const float* __restrict__ variance,
    const float* __restrict__ targets,
    const int*   __restrict__ scope,
    float* __restrict__ out,
    int seg_len, int num_seg)
{
    const int seg = blockIdx.x;
    const int tid = threadIdx.x;           // 0..127
    const long long base = (long long)seg * seg_len;

    const float4* __restrict__ m4 = reinterpret_cast<const float4*>(mean + base);
    const float4* __restrict__ v4 = reinterpret_cast<const float4*>(variance + base);
    const float4* __restrict__ t4 = reinterpret_cast<const float4*>(targets + base);

    float s1 = 0.0f;  // sum exp(a),  a = x + 0.5 y
    float s2 = 0.0f;  // sum exp(t)
    float s3 = 0.0f;  // sum exp(t) * b,  b = x - 0.5 y

    const int nvec = seg_len >> 2;         // float4s per segment (128 for 512)
    for (int i = tid; i < nvec; i += 128) {
        float4 m = m4[i];
        float4 v = v4[i];
        float4 t = t4[i];

        { float h = 0.5f * v.x; float a = m.x + h, b = m.x - h;
          float ea = __expf(a), et = __expf(t.x);
          s1 += ea; s2 += et; s3 += et * b; }
        { float h = 0.5f * v.y; float a = m.y + h, b = m.y - h;
          float ea = __expf(a), et = __expf(t.y);
          s1 += ea; s2 += et; s3 += et * b; }
        { float h = 0.5f * v.z; float a = m.z + h, b = m.z - h;
          float ea = __expf(a), et = __expf(t.z);
          s1 += ea; s2 += et; s3 += et * b; }
        { float h = 0.5f * v.w; float a = m.w + h, b = m.w - h;
          float ea = __expf(a), et = __expf(t.w);
          s1 += ea; s2 += et; s3 += et * b; }
    }

    // Warp reduction (3 values)
    #pragma unroll
    for (int off = 16; off > 0; off >>= 1) {
        s1 += __shfl_down_sync(0xFFFFFFFFu, s1, off);
        s2 += __shfl_down_sync(0xFFFFFFFFu, s2, off);
        s3 += __shfl_down_sync(0xFFFFFFFFu, s3, off);
    }

    __shared__ float sh1[4], sh2[4], sh3[4];
    const int warp = tid >> 5;
    const int lane = tid & 31;
    if (lane == 0) { sh1[warp] = s1; sh2[warp] = s2; sh3[warp] = s3; }
    __syncthreads();

    if (tid == 0) {
        float S1 = sh1[0] + sh1[1] + sh1[2] + sh1[3];
        float S2 = sh2[0] + sh2[1] + sh2[2] + sh2[3];
        float S3 = sh3[0] + sh3[1] + sh3[2] + sh3[3];
        // per_seg = (log(S1) - S3/S2) / scope[seg]
        float val = (__logf(S1) - S3 / S2) / (float)scope[seg];

        const int slot = seg & (NSLOTS - 1);
        const unsigned int per_slot = (unsigned int)(num_seg / NSLOTS); // 128

        // L0: relaxed fire-and-forget RED to spread slot (proven benign, R12).
        atomicAdd(&g_partial[slot][0], val);

        // L1: RELEASE-only ticket on a spread slot: orders the RED above
        // before this CTA's arrival becomes visible. No acquire -> no L1
        // invalidate. Same-address RMW chain accumulates the ordering.
        unsigned int old;
        asm volatile("atom.add.release.gpu.u32 %0, [%1], 1;"
                     : "=r"(old) : "l"(&g_ticket[slot][0]) : "memory");

        if (old == per_slot - 1u) {
            // L2: slot complete (only 128 of these chip-wide). Release so the
            // slot's completed state is ordered before the done-count bump.
            unsigned int old2;
            asm volatile("atom.add.release.gpu.u32 %0, [%1], 1;"
                         : "=r"(old2) : "l"(&g_done) : "memory");

            if (old2 == (unsigned int)NSLOTS - 1u) {
                // Final completer: the ONLY acquire in the whole kernel.
                asm volatile("fence.acquire.gpu;" ::: "memory");
                float s = 0.0f;
                #pragma unroll 16
                for (int k = 0; k < NSLOTS; k++) {
                    float p;
                    asm volatile("ld.relaxed.gpu.f32 %0, [%1];"
                                 : "=f"(p) : "l"(&g_partial[k][0]) : "memory");
                    s += p;
                    g_partial[k][0] = 0.0f;   // reset for next replay
                    g_ticket[k][0]  = 0u;
                }
                out[0] = s / (float)num_seg;
                g_done = 0u;
            }
        }
    }
}

extern "C" void kernel_launch(void* const* d_in, const int* in_sizes, int n_in,
                              void* d_out, int out_size)
{
    // metadata order: mean (N), variance (N), scope (NUM_SEG), targets (N)
    const float* mean     = (const float*)d_in[0];
    const float* variance = (const float*)d_in[1];
    const int*   scope    = (const int*)  d_in[2];
    const float* targets  = (const float*)d_in[3];
    float* out = (float*)d_out;

    const int n       = in_sizes[0];
    const int num_seg = in_sizes[2];
    const int seg_len = n / num_seg;   // 512 for this dataset

    listnet_fused_kernel<<<num_seg, 128>>>(mean, variance, targets, scope, out,
                                           seg_len, num_seg);
}